// round 8
// baseline (speedup 1.0000x reference)
#include <cuda_runtime.h>
#include <cuda_bf16.h>
#include <cstdint>

// Problem constants
#define BB   32
#define CC   128
#define NN   64
#define HID  256

typedef unsigned long long ULL;

// ---------- packed f32x2 helpers ----------
__device__ __forceinline__ ULL pack2(float a, float b) {
    ULL r;
    asm("mov.b64 %0, {%1, %2};" : "=l"(r) : "r"(__float_as_uint(a)), "r"(__float_as_uint(b)));
    return r;
}
__device__ __forceinline__ void unpack2(ULL v, float& a, float& b) {
    unsigned lo, hi;
    asm("mov.b64 {%0, %1}, %2;" : "=r"(lo), "=r"(hi) : "l"(v));
    a = __uint_as_float(lo); b = __uint_as_float(hi);
}
__device__ __forceinline__ ULL fma2(ULL a, ULL b, ULL c) {
    ULL d;
    asm("fma.rn.f32x2 %0, %1, %2, %3;" : "=l"(d) : "l"(a), "l"(b), "l"(c));
    return d;
}

// ---------- device scratch (no allocations allowed) ----------
__device__ float g_rowscore[BB * NN];                 // row scores
__device__ float g_colpart[BB * NN * NN];             // per-(b,h) col partials
__device__ float g_colscore[BB * NN];                 // col scores
__device__ float g_P[2 * BB * NN * NN];               // [kind][b][i][j], kind0=row kind1=col

// =====================================================================
// Kernel 1: fused conv1+relu+conv2+relu+score partials.
// One block per (b,h): 64 pixels (w=0..63), 512 threads.
// thread: wg = tid&7 (owns w = wg*8..wg*8+7), og = tid>>3 (owns o = og*4..og*4+3)
// 4 warps/SMSP for latency hiding; same fma2 floor as the 256-thread version.
// =====================================================================
#define WPAD 65
struct ConvSmem {
    float xs[CC * NN];          // 128x64 input slice        (32 KB)
    float h1[HID * NN];         // 256x64 hidden             (64 KB)
    float wbuf[HID * WPAD];     // weight chunk [256][65]    (65 KB)
    float wcol[HID];            // w_col[:,h]
    float colred[NN];
    float rowred;
};

__global__ void __launch_bounds__(512, 1) conv_score_kernel(
    const float* __restrict__ x,
    const float* __restrict__ w1, const float* __restrict__ b1,
    const float* __restrict__ w2, const float* __restrict__ b2,
    const float* __restrict__ w_row, const float* __restrict__ b_row,
    const float* __restrict__ w_col)
{
    extern __shared__ unsigned char dyn_smem[];
    ConvSmem* sm = reinterpret_cast<ConvSmem*>(dyn_smem);

    const int tid = threadIdx.x;
    const int bh  = blockIdx.x;
    const int b   = bh >> 6;
    const int h   = bh & 63;
    const int wg  = tid & 7;
    const int og  = tid >> 3;          // 0..63, owns 4 output channels

    if (tid < NN) sm->colred[tid] = 0.f;
    if (tid == 0) sm->rowred = 0.f;
    if (tid < HID) sm->wcol[tid] = __ldg(&w_col[tid * NN + h]);

    // ---- load x[b, :, h, :] into xs[c][w] (coalesced float4) ----
    {
        const float4* xg = reinterpret_cast<const float4*>(x + (size_t)b * CC * NN * NN + (size_t)h * NN);
        #pragma unroll
        for (int j = 0; j < 4; j++) {
            int idx = tid + j * 512;          // 2048 float4 total
            int c   = idx >> 4;
            int w4  = idx & 15;
            float4 v = xg[(size_t)c * (NN * NN / 4) + w4];
            *reinterpret_cast<float4*>(&sm->xs[c * NN + w4 * 4]) = v;
        }
    }

    // ---- accumulators (4 o x 4 w-pairs), init with b1 ----
    ULL acc[4][4];
    #pragma unroll
    for (int i = 0; i < 4; i++) {
        float bv = __ldg(&b1[og * 4 + i]);
        ULL p = pack2(bv, bv);
        acc[i][0] = p; acc[i][1] = p; acc[i][2] = p; acc[i][3] = p;
    }

    // ---- conv1: 2 chunks of 64 input channels ----
    for (int cc = 0; cc < 2; cc++) {
        const float4* g4 = reinterpret_cast<const float4*>(w1);
        #pragma unroll
        for (int j = 0; j < 8; j++) {
            int idx = tid + j * 512;          // 4096 float4
            int r   = idx >> 4;
            int c4  = idx & 15;
            float4 v = g4[r * (CC / 4) + cc * 16 + c4];
            float* d = &sm->wbuf[r * WPAD + c4 * 4];
            d[0] = v.x; d[1] = v.y; d[2] = v.z; d[3] = v.w;
        }
        __syncthreads();

        #pragma unroll 4
        for (int c = 0; c < 64; c++) {
            const ULL* xrow = reinterpret_cast<const ULL*>(&sm->xs[(cc * 64 + c) * NN + wg * 8]);
            ULL xv0 = xrow[0], xv1 = xrow[1], xv2 = xrow[2], xv3 = xrow[3];
            #pragma unroll
            for (int i = 0; i < 4; i++) {
                float wv = sm->wbuf[(og * 4 + i) * WPAD + c];
                ULL wp2 = pack2(wv, wv);
                acc[i][0] = fma2(xv0, wp2, acc[i][0]);
                acc[i][1] = fma2(xv1, wp2, acc[i][1]);
                acc[i][2] = fma2(xv2, wp2, acc[i][2]);
                acc[i][3] = fma2(xv3, wp2, acc[i][3]);
            }
        }
        __syncthreads();
    }

    // ---- relu, store h1, re-init acc with b2 ----
    #pragma unroll
    for (int i = 0; i < 4; i++) {
        int o = og * 4 + i;
        #pragma unroll
        for (int wp = 0; wp < 4; wp++) {
            float a0, a1; unpack2(acc[i][wp], a0, a1);
            a0 = fmaxf(a0, 0.f); a1 = fmaxf(a1, 0.f);
            *reinterpret_cast<ULL*>(&sm->h1[o * NN + wg * 8 + wp * 2]) = pack2(a0, a1);
        }
        float bv = __ldg(&b2[o]);
        ULL p = pack2(bv, bv);
        acc[i][0] = p; acc[i][1] = p; acc[i][2] = p; acc[i][3] = p;
    }
    __syncthreads();

    // ---- conv2: 4 chunks of 64 channels ----
    for (int cc = 0; cc < 4; cc++) {
        const float4* g4 = reinterpret_cast<const float4*>(w2);
        #pragma unroll
        for (int j = 0; j < 8; j++) {
            int idx = tid + j * 512;
            int r   = idx >> 4;
            int c4  = idx & 15;
            float4 v = g4[r * (HID / 4) + cc * 16 + c4];
            float* d = &sm->wbuf[r * WPAD + c4 * 4];
            d[0] = v.x; d[1] = v.y; d[2] = v.z; d[3] = v.w;
        }
        __syncthreads();

        #pragma unroll 4
        for (int c = 0; c < 64; c++) {
            const ULL* xrow = reinterpret_cast<const ULL*>(&sm->h1[(cc * 64 + c) * NN + wg * 8]);
            ULL xv0 = xrow[0], xv1 = xrow[1], xv2 = xrow[2], xv3 = xrow[3];
            #pragma unroll
            for (int i = 0; i < 4; i++) {
                float wv = sm->wbuf[(og * 4 + i) * WPAD + c];
                ULL wp2 = pack2(wv, wv);
                acc[i][0] = fma2(xv0, wp2, acc[i][0]);
                acc[i][1] = fma2(xv1, wp2, acc[i][1]);
                acc[i][2] = fma2(xv2, wp2, acc[i][2]);
                acc[i][3] = fma2(xv3, wp2, acc[i][3]);
            }
        }
        __syncthreads();
    }

    // ---- relu h2 (registers) + score partials ----
    float rowp = 0.f;
    float colp[8];
    #pragma unroll
    for (int j = 0; j < 8; j++) colp[j] = 0.f;

    #pragma unroll
    for (int i = 0; i < 4; i++) {
        int o = og * 4 + i;
        float wc = sm->wcol[o];
        #pragma unroll
        for (int wp = 0; wp < 4; wp++) {
            float a0, a1; unpack2(acc[i][wp], a0, a1);
            a0 = fmaxf(a0, 0.f); a1 = fmaxf(a1, 0.f);
            float2 wr = __ldg(reinterpret_cast<const float2*>(&w_row[o * NN + wg * 8 + wp * 2]));
            rowp += a0 * wr.x + a1 * wr.y;
            colp[wp * 2]     += a0 * wc;
            colp[wp * 2 + 1] += a1 * wc;
        }
    }
    // full-warp reduce rowp -> 1 atomic per warp
    #pragma unroll
    for (int m = 16; m >= 1; m >>= 1)
        rowp += __shfl_xor_sync(0xffffffffu, rowp, m);
    if ((tid & 31) == 0) atomicAdd(&sm->rowred, rowp);

    // reduce colp across the 4 og values within the warp (lanes tid^8, tid^16 share wg)
    #pragma unroll
    for (int j = 0; j < 8; j++) {
        colp[j] += __shfl_xor_sync(0xffffffffu, colp[j], 8);
        colp[j] += __shfl_xor_sync(0xffffffffu, colp[j], 16);
    }
    if ((tid & 31) < 8) {
        #pragma unroll
        for (int j = 0; j < 8; j++) atomicAdd(&sm->colred[wg * 8 + j], colp[j]);
    }
    __syncthreads();

    if (tid == 0)  g_rowscore[bh] = sm->rowred + __ldg(&b_row[0]);
    if (tid < NN)  g_colpart[bh * NN + tid] = sm->colred[tid];
}

// =====================================================================
// Kernel 2: reduce col partials over h
// =====================================================================
__global__ void col_reduce_kernel(const float* __restrict__ b_col)
{
    int b = blockIdx.x;
    int w = threadIdx.x;
    float s = __ldg(&b_col[0]);
    #pragma unroll 8
    for (int hh = 0; hh < NN; hh++) s += g_colpart[(b * NN + hh) * NN + w];
    g_colscore[b * NN + w] = s;
}

// =====================================================================
// Kernel 3: differentiable bitonic sort -> permutation matrix P
// 64 blocks: block s -> kind = s>>5 (0=row, 1=col), b = s&31
// =====================================================================
#define PPAD 65
__global__ void __launch_bounds__(256) sort_kernel()
{
    __shared__ float P[NN * PPAD];
    __shared__ float xsh[NN];
    __shared__ float alph[32];
    __shared__ int   pa[32], pb[32];

    const int tid  = threadIdx.x;
    const int s    = blockIdx.x;
    const int kind = s >> 5;
    const int b    = s & 31;
    const float* sc = kind ? g_colscore : g_rowscore;

    if (tid < NN) xsh[tid] = sc[b * NN + tid];
    for (int idx = tid; idx < NN * NN; idx += 256) {
        int r = idx >> 6, c = idx & 63;
        P[r * PPAD + c] = (r == c) ? 1.f : 0.f;
    }
    __syncthreads();

    for (int blk = 0; blk < 6; blk++) {
        for (int lay = 0; lay <= blk; lay++) {
            int m = 1 << (blk - lay);
            if (tid < 32) {
                int q  = tid;
                int ix = ((q & ~(m - 1)) << 1) | (q & (m - 1));
                int a = ix, bidx = ix + m;
                if ((ix >> (blk + 1)) & 1) { int t = a; a = bidx; bidx = t; }
                pa[q] = a; pb[q] = bidx;
                float xa = xsh[a], xb = xsh[bidx];
                float al = atanf((xb - xa) * 50.f) * 0.31830988618379067f + 0.5f;
                alph[q] = al;
                xsh[a]    = al * xa + (1.f - al) * xb;
                xsh[bidx] = (1.f - al) * xa + al * xb;
            }
            __syncthreads();
            #pragma unroll
            for (int it = 0; it < 8; it++) {
                int idx = tid + it * 256;             // 2048 = 64 rows x 32 pairs
                int r = idx >> 5, q = idx & 31;
                int a = pa[q], bidx = pb[q];
                float al = alph[q];
                float Pa = P[r * PPAD + a], Pb = P[r * PPAD + bidx];
                P[r * PPAD + a]    = al * Pa + (1.f - al) * Pb;
                P[r * PPAD + bidx] = (1.f - al) * Pa + al * Pb;
            }
            __syncthreads();
        }
    }

    for (int idx = tid; idx < NN * NN; idx += 256)
        g_P[(size_t)(kind * BB + b) * NN * NN + idx] = P[(idx >> 6) * PPAD + (idx & 63)];
}

// =====================================================================
// Kernel 4: out[b,c] = P_col * (P_row * X)^T     (one block per (b,c))
// 128 threads, 8i x 4k register tile -> halves smem traffic per fma,
// moving the kernel from L1-bound (86%) to fma-bound.
// =====================================================================
#define YPAD 68
struct ApplySmem {
    float Xs[NN * NN];      // 4096
    float Prs[NN * PPAD];   // 4160
    float Pcs[NN * PPAD];   // 4160
    float Yt[NN * YPAD];    // 4352 (stores (P_row X)^T)
};

__global__ void __launch_bounds__(128) apply_kernel(
    const float* __restrict__ x, float* __restrict__ out)
{
    extern __shared__ unsigned char dyn_smem[];
    ApplySmem* sm = reinterpret_cast<ApplySmem*>(dyn_smem);

    const int tid = threadIdx.x;
    const int bc  = blockIdx.x;
    const int b   = bc >> 7;

    // load X (this (b,c) 64x64 tile)
    {
        const float4* xg = reinterpret_cast<const float4*>(x) + (size_t)bc * (NN * NN / 4);
        float4* Xs4 = reinterpret_cast<float4*>(sm->Xs);
        #pragma unroll
        for (int j = 0; j < 8; j++) Xs4[tid + j * 128] = xg[tid + j * 128];
    }
    // load P_row, P_col into padded smem
    {
        const float4* pr4 = reinterpret_cast<const float4*>(&g_P[(size_t)b * NN * NN]);
        const float4* pc4 = reinterpret_cast<const float4*>(&g_P[(size_t)(BB + b) * NN * NN]);
        #pragma unroll
        for (int j = 0; j < 8; j++) {
            int idx = tid + j * 128;
            int l = idx * 4, r = l >> 6, c = l & 63;
            float4 v = pr4[idx];
            float* d = &sm->Prs[r * PPAD + c];
            d[0] = v.x; d[1] = v.y; d[2] = v.z; d[3] = v.w;
            float4 u = pc4[idx];
            float* e = &sm->Pcs[r * PPAD + c];
            e[0] = u.x; e[1] = u.y; e[2] = u.z; e[3] = u.w;
        }
    }
    __syncthreads();

    const int ig = tid >> 4, kg = tid & 15;   // ig 0..7, kg 0..15
    const int i0 = ig * 8,   k0 = kg * 4;

    // phase 1: Y[i][k] = sum_j Prs[i][j] * X[j][k]   (8 i x 4 k per thread)
    ULL acc[8][2];
    #pragma unroll
    for (int ii = 0; ii < 8; ii++) { acc[ii][0] = 0ull; acc[ii][1] = 0ull; }

    #pragma unroll 4
    for (int j = 0; j < NN; j++) {
        const ULL* xp = reinterpret_cast<const ULL*>(&sm->Xs[j * NN + k0]);
        ULL xv0 = xp[0], xv1 = xp[1];
        #pragma unroll
        for (int ii = 0; ii < 8; ii++) {
            float p = sm->Prs[(i0 + ii) * PPAD + j];
            ULL pp = pack2(p, p);
            acc[ii][0] = fma2(xv0, pp, acc[ii][0]);
            acc[ii][1] = fma2(xv1, pp, acc[ii][1]);
        }
    }
    // write Y transposed: Yt[k][i] = Y[i][k]
    {
        float yv[8][4];
        #pragma unroll
        for (int ii = 0; ii < 8; ii++) {
            unpack2(acc[ii][0], yv[ii][0], yv[ii][1]);
            unpack2(acc[ii][1], yv[ii][2], yv[ii][3]);
        }
        #pragma unroll
        for (int kk = 0; kk < 4; kk++) {
            float4 v0 = make_float4(yv[0][kk], yv[1][kk], yv[2][kk], yv[3][kk]);
            float4 v1 = make_float4(yv[4][kk], yv[5][kk], yv[6][kk], yv[7][kk]);
            *reinterpret_cast<float4*>(&sm->Yt[(k0 + kk) * YPAD + i0])     = v0;
            *reinterpret_cast<float4*>(&sm->Yt[(k0 + kk) * YPAD + i0 + 4]) = v1;
        }
    }
    __syncthreads();

    // phase 2: out[i][k] = sum_j Pcs[i][j] * Yt[j][k]
    #pragma unroll
    for (int ii = 0; ii < 8; ii++) { acc[ii][0] = 0ull; acc[ii][1] = 0ull; }

    #pragma unroll 4
    for (int j = 0; j < NN; j++) {
        const ULL* yp = reinterpret_cast<const ULL*>(&sm->Yt[j * YPAD + k0]);
        ULL yv0 = yp[0], yv1 = yp[1];
        #pragma unroll
        for (int ii = 0; ii < 8; ii++) {
            float p = sm->Pcs[(i0 + ii) * PPAD + j];
            ULL pp = pack2(p, p);
            acc[ii][0] = fma2(yv0, pp, acc[ii][0]);
            acc[ii][1] = fma2(yv1, pp, acc[ii][1]);
        }
    }

    float* og = out + (size_t)bc * NN * NN;
    #pragma unroll
    for (int ii = 0; ii < 8; ii++) {
        float o0, o1, o2, o3;
        unpack2(acc[ii][0], o0, o1);
        unpack2(acc[ii][1], o2, o3);
        *reinterpret_cast<float4*>(&og[(i0 + ii) * NN + k0]) = make_float4(o0, o1, o2, o3);
    }
}

// =====================================================================
// launcher
// =====================================================================
extern "C" void kernel_launch(void* const* d_in, const int* in_sizes, int n_in,
                              void* d_out, int out_size)
{
    const float* x     = (const float*)d_in[0];
    const float* w1    = (const float*)d_in[1];
    const float* b1    = (const float*)d_in[2];
    const float* w2    = (const float*)d_in[3];
    const float* b2    = (const float*)d_in[4];
    const float* w_row = (const float*)d_in[5];
    const float* b_row = (const float*)d_in[6];
    const float* w_col = (const float*)d_in[7];
    const float* b_col = (const float*)d_in[8];
    float* out = (float*)d_out;

    const int conv_smem  = (int)sizeof(ConvSmem);
    const int apply_smem = (int)sizeof(ApplySmem);
    cudaFuncSetAttribute(conv_score_kernel, cudaFuncAttributeMaxDynamicSharedMemorySize, conv_smem);
    cudaFuncSetAttribute(apply_kernel,      cudaFuncAttributeMaxDynamicSharedMemorySize, apply_smem);

    conv_score_kernel<<<BB * NN, 512, conv_smem>>>(x, w1, b1, w2, b2, w_row, b_row, w_col);
    col_reduce_kernel<<<BB, NN>>>(b_col);
    sort_kernel<<<2 * BB, 256>>>();
    apply_kernel<<<BB * CC, 128, apply_smem>>>(x, out);
}

// round 9
// speedup vs baseline: 1.1629x; 1.1629x over previous
#include <cuda_runtime.h>
#include <cuda_bf16.h>
#include <cstdint>

// Problem constants
#define BB   32
#define CC   128
#define NN   64
#define HID  256

typedef unsigned long long ULL;

// ---------- packed f32x2 helpers ----------
__device__ __forceinline__ ULL pack2(float a, float b) {
    ULL r;
    asm("mov.b64 %0, {%1, %2};" : "=l"(r) : "r"(__float_as_uint(a)), "r"(__float_as_uint(b)));
    return r;
}
__device__ __forceinline__ void unpack2(ULL v, float& a, float& b) {
    unsigned lo, hi;
    asm("mov.b64 {%0, %1}, %2;" : "=r"(lo), "=r"(hi) : "l"(v));
    a = __uint_as_float(lo); b = __uint_as_float(hi);
}
__device__ __forceinline__ ULL fma2(ULL a, ULL b, ULL c) {
    ULL d;
    asm("fma.rn.f32x2 %0, %1, %2, %3;" : "=l"(d) : "l"(a), "l"(b), "l"(c));
    return d;
}

// ---------- device scratch (no allocations allowed) ----------
__device__ float g_rowscore[BB * NN];                 // row scores
__device__ float g_colpart[BB * NN * NN];             // per-(b,h) col partials
__device__ float g_colscore[BB * NN];                 // col scores
__device__ float g_P[2 * BB * NN * NN];               // [kind][b][i][j], kind0=row kind1=col

// =====================================================================
// Kernel 1: fused conv1+relu+conv2+relu+score partials.
// One block per (b,h): 64 pixels, 512 threads.
//   wg = tid & 15  -> owns pixels w = wg*4 .. wg*4+3
//   og = tid >> 4  -> owns outputs o = og*8 .. og*8+7
// Weights staged in smem PRE-PACKED as f32x2 pairs (chunks of 32 channels).
// Per inner channel per thread: 1 LDS.128 + 8 LDS.64 + 16 fma2 -> fma-bound.
// =====================================================================
#define CH    32          // channels per weight chunk
#define CHP   33          // padded (in ULL units)
struct ConvSmem {
    float xs[CC * NN];          // 128x64 input slice        (32 KB)
    float h1[HID * NN];         // 256x64 hidden             (64 KB)
    ULL   wpk[HID * CHP];       // packed weight chunk       (66 KB)
    float wcol[HID];            // w_col[:,h]
    float colred[NN];
    float rowred;
};

__global__ void __launch_bounds__(512, 1) conv_score_kernel(
    const float* __restrict__ x,
    const float* __restrict__ w1, const float* __restrict__ b1,
    const float* __restrict__ w2, const float* __restrict__ b2,
    const float* __restrict__ w_row, const float* __restrict__ b_row,
    const float* __restrict__ w_col)
{
    extern __shared__ unsigned char dyn_smem[];
    ConvSmem* sm = reinterpret_cast<ConvSmem*>(dyn_smem);

    const int tid = threadIdx.x;
    const int bh  = blockIdx.x;
    const int b   = bh >> 6;
    const int h   = bh & 63;
    const int wg  = tid & 15;          // pixel group (4 pixels)
    const int og  = tid >> 4;          // output group (8 outputs)

    if (tid < NN) sm->colred[tid] = 0.f;
    if (tid == 0) sm->rowred = 0.f;
    if (tid < HID) sm->wcol[tid] = __ldg(&w_col[tid * NN + h]);

    // ---- load x[b, :, h, :] into xs[c][w] (coalesced float4) ----
    {
        const float4* xg = reinterpret_cast<const float4*>(x + (size_t)b * CC * NN * NN + (size_t)h * NN);
        #pragma unroll
        for (int j = 0; j < 4; j++) {
            int idx = tid + j * 512;          // 2048 float4 total
            int c   = idx >> 4;
            int w4  = idx & 15;
            float4 v = xg[(size_t)c * (NN * NN / 4) + w4];
            *reinterpret_cast<float4*>(&sm->xs[c * NN + w4 * 4]) = v;
        }
    }

    // ---- accumulators (8 outputs x 2 pixel-pairs), init with b1 ----
    ULL acc[8][2];
    #pragma unroll
    for (int i = 0; i < 8; i++) {
        float bv = __ldg(&b1[og * 8 + i]);
        ULL p = pack2(bv, bv);
        acc[i][0] = p; acc[i][1] = p;
    }

    // ---- conv1: 4 chunks of 32 input channels ----
    for (int cc = 0; cc < 4; cc++) {
        // stage w1[:, cc*32 .. +31] into wpk, pre-packed (8192 floats = 2048 float4)
        const float4* g4 = reinterpret_cast<const float4*>(w1);
        #pragma unroll
        for (int j = 0; j < 4; j++) {
            int idx = tid + j * 512;
            int r   = idx >> 3;               // output channel (8 float4 per row of 32)
            int c4  = idx & 7;
            float4 v = g4[r * (CC / 4) + cc * 8 + c4];
            ULL* d = &sm->wpk[r * CHP + c4 * 4];
            d[0] = pack2(v.x, v.x); d[1] = pack2(v.y, v.y);
            d[2] = pack2(v.z, v.z); d[3] = pack2(v.w, v.w);
        }
        __syncthreads();

        #pragma unroll 4
        for (int c = 0; c < CH; c++) {
            ulonglong2 xv = *reinterpret_cast<const ulonglong2*>(&sm->xs[(cc * CH + c) * NN + wg * 4]);
            const ULL* wrow = &sm->wpk[(og * 8) * CHP + c];
            #pragma unroll
            for (int i = 0; i < 8; i++) {
                ULL wp2 = wrow[i * CHP];
                acc[i][0] = fma2(xv.x, wp2, acc[i][0]);
                acc[i][1] = fma2(xv.y, wp2, acc[i][1]);
            }
        }
        __syncthreads();
    }

    // ---- relu, store h1, re-init acc with b2 ----
    #pragma unroll
    for (int i = 0; i < 8; i++) {
        int o = og * 8 + i;
        float a0, a1, a2, a3;
        unpack2(acc[i][0], a0, a1);
        unpack2(acc[i][1], a2, a3);
        a0 = fmaxf(a0, 0.f); a1 = fmaxf(a1, 0.f);
        a2 = fmaxf(a2, 0.f); a3 = fmaxf(a3, 0.f);
        *reinterpret_cast<float4*>(&sm->h1[o * NN + wg * 4]) = make_float4(a0, a1, a2, a3);
        float bv = __ldg(&b2[o]);
        ULL p = pack2(bv, bv);
        acc[i][0] = p; acc[i][1] = p;
    }
    __syncthreads();

    // ---- conv2: 8 chunks of 32 channels ----
    for (int cc = 0; cc < 8; cc++) {
        const float4* g4 = reinterpret_cast<const float4*>(w2);
        #pragma unroll
        for (int j = 0; j < 4; j++) {
            int idx = tid + j * 512;
            int r   = idx >> 3;
            int c4  = idx & 7;
            float4 v = g4[r * (HID / 4) + cc * 8 + c4];
            ULL* d = &sm->wpk[r * CHP + c4 * 4];
            d[0] = pack2(v.x, v.x); d[1] = pack2(v.y, v.y);
            d[2] = pack2(v.z, v.z); d[3] = pack2(v.w, v.w);
        }
        __syncthreads();

        #pragma unroll 4
        for (int c = 0; c < CH; c++) {
            ulonglong2 xv = *reinterpret_cast<const ulonglong2*>(&sm->h1[(cc * CH + c) * NN + wg * 4]);
            const ULL* wrow = &sm->wpk[(og * 8) * CHP + c];
            #pragma unroll
            for (int i = 0; i < 8; i++) {
                ULL wp2 = wrow[i * CHP];
                acc[i][0] = fma2(xv.x, wp2, acc[i][0]);
                acc[i][1] = fma2(xv.y, wp2, acc[i][1]);
            }
        }
        __syncthreads();
    }

    // ---- relu h2 (registers) + score partials ----
    float rowp = 0.f;
    float colp[4];
    #pragma unroll
    for (int j = 0; j < 4; j++) colp[j] = 0.f;

    #pragma unroll
    for (int i = 0; i < 8; i++) {
        int o = og * 8 + i;
        float wc = sm->wcol[o];
        float a0, a1, a2, a3;
        unpack2(acc[i][0], a0, a1);
        unpack2(acc[i][1], a2, a3);
        a0 = fmaxf(a0, 0.f); a1 = fmaxf(a1, 0.f);
        a2 = fmaxf(a2, 0.f); a3 = fmaxf(a3, 0.f);
        float4 wr = __ldg(reinterpret_cast<const float4*>(&w_row[o * NN + wg * 4]));
        rowp += a0 * wr.x + a1 * wr.y + a2 * wr.z + a3 * wr.w;
        colp[0] += a0 * wc; colp[1] += a1 * wc;
        colp[2] += a2 * wc; colp[3] += a3 * wc;
    }
    // full-warp reduce rowp -> 1 atomic per warp
    #pragma unroll
    for (int m = 16; m >= 1; m >>= 1)
        rowp += __shfl_xor_sync(0xffffffffu, rowp, m);
    if ((tid & 31) == 0) atomicAdd(&sm->rowred, rowp);

    // reduce colp across the 2 og halves of the warp (lane^16 shares wg)
    #pragma unroll
    for (int j = 0; j < 4; j++)
        colp[j] += __shfl_xor_sync(0xffffffffu, colp[j], 16);
    if ((tid & 31) < 16) {
        #pragma unroll
        for (int j = 0; j < 4; j++) atomicAdd(&sm->colred[wg * 4 + j], colp[j]);
    }
    __syncthreads();

    if (tid == 0)  g_rowscore[bh] = sm->rowred + __ldg(&b_row[0]);
    if (tid < NN)  g_colpart[bh * NN + tid] = sm->colred[tid];
}

// =====================================================================
// Kernel 2: reduce col partials over h
// =====================================================================
__global__ void col_reduce_kernel(const float* __restrict__ b_col)
{
    int b = blockIdx.x;
    int w = threadIdx.x;
    float s = __ldg(&b_col[0]);
    #pragma unroll 8
    for (int hh = 0; hh < NN; hh++) s += g_colpart[(b * NN + hh) * NN + w];
    g_colscore[b * NN + w] = s;
}

// =====================================================================
// Kernel 3: differentiable bitonic sort -> permutation matrix P
// =====================================================================
#define PPAD 65
__global__ void __launch_bounds__(256) sort_kernel()
{
    __shared__ float P[NN * PPAD];
    __shared__ float xsh[NN];
    __shared__ float alph[32];
    __shared__ int   pa[32], pb[32];

    const int tid  = threadIdx.x;
    const int s    = blockIdx.x;
    const int kind = s >> 5;
    const int b    = s & 31;
    const float* sc = kind ? g_colscore : g_rowscore;

    if (tid < NN) xsh[tid] = sc[b * NN + tid];
    for (int idx = tid; idx < NN * NN; idx += 256) {
        int r = idx >> 6, c = idx & 63;
        P[r * PPAD + c] = (r == c) ? 1.f : 0.f;
    }
    __syncthreads();

    for (int blk = 0; blk < 6; blk++) {
        for (int lay = 0; lay <= blk; lay++) {
            int m = 1 << (blk - lay);
            if (tid < 32) {
                int q  = tid;
                int ix = ((q & ~(m - 1)) << 1) | (q & (m - 1));
                int a = ix, bidx = ix + m;
                if ((ix >> (blk + 1)) & 1) { int t = a; a = bidx; bidx = t; }
                pa[q] = a; pb[q] = bidx;
                float xa = xsh[a], xb = xsh[bidx];
                float al = atanf((xb - xa) * 50.f) * 0.31830988618379067f + 0.5f;
                alph[q] = al;
                xsh[a]    = al * xa + (1.f - al) * xb;
                xsh[bidx] = (1.f - al) * xa + al * xb;
            }
            __syncthreads();
            #pragma unroll
            for (int it = 0; it < 8; it++) {
                int idx = tid + it * 256;             // 2048 = 64 rows x 32 pairs
                int r = idx >> 5, q = idx & 31;
                int a = pa[q], bidx = pb[q];
                float al = alph[q];
                float Pa = P[r * PPAD + a], Pb = P[r * PPAD + bidx];
                P[r * PPAD + a]    = al * Pa + (1.f - al) * Pb;
                P[r * PPAD + bidx] = (1.f - al) * Pa + al * Pb;
            }
            __syncthreads();
        }
    }

    for (int idx = tid; idx < NN * NN; idx += 256)
        g_P[(size_t)(kind * BB + b) * NN * NN + idx] = P[(idx >> 6) * PPAD + (idx & 63)];
}

// =====================================================================
// Kernel 4: out[b,c] = P_col * (P_row * X)^T     (one block per (b,c))
// 128 threads, 8i x 4k register tile (round-8 version: 107us measured).
// =====================================================================
#define YPAD 68
struct ApplySmem {
    float Xs[NN * NN];      // 4096
    float Prs[NN * PPAD];   // 4160
    float Pcs[NN * PPAD];   // 4160
    float Yt[NN * YPAD];    // 4352 (stores (P_row X)^T)
};

__global__ void __launch_bounds__(128) apply_kernel(
    const float* __restrict__ x, float* __restrict__ out)
{
    extern __shared__ unsigned char dyn_smem[];
    ApplySmem* sm = reinterpret_cast<ApplySmem*>(dyn_smem);

    const int tid = threadIdx.x;
    const int bc  = blockIdx.x;
    const int b   = bc >> 7;

    // load X (this (b,c) 64x64 tile)
    {
        const float4* xg = reinterpret_cast<const float4*>(x) + (size_t)bc * (NN * NN / 4);
        float4* Xs4 = reinterpret_cast<float4*>(sm->Xs);
        #pragma unroll
        for (int j = 0; j < 8; j++) Xs4[tid + j * 128] = xg[tid + j * 128];
    }
    // load P_row, P_col into padded smem
    {
        const float4* pr4 = reinterpret_cast<const float4*>(&g_P[(size_t)b * NN * NN]);
        const float4* pc4 = reinterpret_cast<const float4*>(&g_P[(size_t)(BB + b) * NN * NN]);
        #pragma unroll
        for (int j = 0; j < 8; j++) {
            int idx = tid + j * 128;
            int l = idx * 4, r = l >> 6, c = l & 63;
            float4 v = pr4[idx];
            float* d = &sm->Prs[r * PPAD + c];
            d[0] = v.x; d[1] = v.y; d[2] = v.z; d[3] = v.w;
            float4 u = pc4[idx];
            float* e = &sm->Pcs[r * PPAD + c];
            e[0] = u.x; e[1] = u.y; e[2] = u.z; e[3] = u.w;
        }
    }
    __syncthreads();

    const int ig = tid >> 4, kg = tid & 15;   // ig 0..7, kg 0..15
    const int i0 = ig * 8,   k0 = kg * 4;

    // phase 1: Y[i][k] = sum_j Prs[i][j] * X[j][k]   (8 i x 4 k per thread)
    ULL acc[8][2];
    #pragma unroll
    for (int ii = 0; ii < 8; ii++) { acc[ii][0] = 0ull; acc[ii][1] = 0ull; }

    #pragma unroll 4
    for (int j = 0; j < NN; j++) {
        const ULL* xp = reinterpret_cast<const ULL*>(&sm->Xs[j * NN + k0]);
        ULL xv0 = xp[0], xv1 = xp[1];
        #pragma unroll
        for (int ii = 0; ii < 8; ii++) {
            float p = sm->Prs[(i0 + ii) * PPAD + j];
            ULL pp = pack2(p, p);
            acc[ii][0] = fma2(xv0, pp, acc[ii][0]);
            acc[ii][1] = fma2(xv1, pp, acc[ii][1]);
        }
    }
    // write Y transposed: Yt[k][i] = Y[i][k]
    {
        float yv[8][4];
        #pragma unroll
        for (int ii = 0; ii < 8; ii++) {
            unpack2(acc[ii][0], yv[ii][0], yv[ii][1]);
            unpack2(acc[ii][1], yv[ii][2], yv[ii][3]);
        }
        #pragma unroll
        for (int kk = 0; kk < 4; kk++) {
            float4 v0 = make_float4(yv[0][kk], yv[1][kk], yv[2][kk], yv[3][kk]);
            float4 v1 = make_float4(yv[4][kk], yv[5][kk], yv[6][kk], yv[7][kk]);
            *reinterpret_cast<float4*>(&sm->Yt[(k0 + kk) * YPAD + i0])     = v0;
            *reinterpret_cast<float4*>(&sm->Yt[(k0 + kk) * YPAD + i0 + 4]) = v1;
        }
    }
    __syncthreads();

    // phase 2: out[i][k] = sum_j Pcs[i][j] * Yt[j][k]
    #pragma unroll
    for (int ii = 0; ii < 8; ii++) { acc[ii][0] = 0ull; acc[ii][1] = 0ull; }

    #pragma unroll 4
    for (int j = 0; j < NN; j++) {
        const ULL* yp = reinterpret_cast<const ULL*>(&sm->Yt[j * YPAD + k0]);
        ULL yv0 = yp[0], yv1 = yp[1];
        #pragma unroll
        for (int ii = 0; ii < 8; ii++) {
            float p = sm->Pcs[(i0 + ii) * PPAD + j];
            ULL pp = pack2(p, p);
            acc[ii][0] = fma2(yv0, pp, acc[ii][0]);
            acc[ii][1] = fma2(yv1, pp, acc[ii][1]);
        }
    }

    float* og = out + (size_t)bc * NN * NN;
    #pragma unroll
    for (int ii = 0; ii < 8; ii++) {
        float o0, o1, o2, o3;
        unpack2(acc[ii][0], o0, o1);
        unpack2(acc[ii][1], o2, o3);
        *reinterpret_cast<float4*>(&og[(ii + i0) * NN + k0]) = make_float4(o0, o1, o2, o3);
    }
}

// =====================================================================
// launcher
// =====================================================================
extern "C" void kernel_launch(void* const* d_in, const int* in_sizes, int n_in,
                              void* d_out, int out_size)
{
    const float* x     = (const float*)d_in[0];
    const float* w1    = (const float*)d_in[1];
    const float* b1    = (const float*)d_in[2];
    const float* w2    = (const float*)d_in[3];
    const float* b2    = (const float*)d_in[4];
    const float* w_row = (const float*)d_in[5];
    const float* b_row = (const float*)d_in[6];
    const float* w_col = (const float*)d_in[7];
    const float* b_col = (const float*)d_in[8];
    float* out = (float*)d_out;

    const int conv_smem  = (int)sizeof(ConvSmem);
    const int apply_smem = (int)sizeof(ApplySmem);
    cudaFuncSetAttribute(conv_score_kernel, cudaFuncAttributeMaxDynamicSharedMemorySize, conv_smem);
    cudaFuncSetAttribute(apply_kernel,      cudaFuncAttributeMaxDynamicSharedMemorySize, apply_smem);

    conv_score_kernel<<<BB * NN, 512, conv_smem>>>(x, w1, b1, w2, b2, w_row, b_row, w_col);
    col_reduce_kernel<<<BB, NN>>>(b_col);
    sort_kernel<<<2 * BB, 256>>>();
    apply_kernel<<<BB * CC, 128, apply_smem>>>(x, out);
}

// round 10
// speedup vs baseline: 1.7675x; 1.5200x over previous
#include <cuda_runtime.h>
#include <cuda_bf16.h>
#include <cstdint>

// Problem constants
#define BB   32
#define CC   128
#define NN   64
#define HID  256
#define NPX  (BB * NN * NN)        // 131072 pixels

typedef unsigned long long ULL;

// ---------- packed f32x2 helpers ----------
__device__ __forceinline__ ULL pack2(float a, float b) {
    ULL r;
    asm("mov.b64 %0, {%1, %2};" : "=l"(r) : "r"(__float_as_uint(a)), "r"(__float_as_uint(b)));
    return r;
}
__device__ __forceinline__ void unpack2(ULL v, float& a, float& b) {
    unsigned lo, hi;
    asm("mov.b64 {%0, %1}, %2;" : "=r"(lo), "=r"(hi) : "l"(v));
    a = __uint_as_float(lo); b = __uint_as_float(hi);
}
__device__ __forceinline__ ULL fma2(ULL a, ULL b, ULL c) {
    ULL d;
    asm("fma.rn.f32x2 %0, %1, %2, %3;" : "=l"(d) : "l"(a), "l"(b), "l"(c));
    return d;
}

// ---------- device scratch (no allocations allowed) ----------
__device__ float g_h1[(size_t)HID * NPX];             // 134 MB hidden activations
__device__ float g_rowpart[2 * BB * NN];              // per-half row-score partials
__device__ float g_cp[2 * 1024 * NN];                 // per-(half, pxtile) col partials
__device__ float g_rowscore[BB * NN];
__device__ float g_colscore[BB * NN];
__device__ float g_P[2 * BB * NN * NN];               // [kind][b][i][j]

// =====================================================================
// Kernel 1: conv1 + relu  ->  g_h1
// GEMM: h1[o=256, p=131072] = relu(W1[256,128] @ X[128,p] + b1)
// grid (1024 px-tiles of 128, 2 out-halves), 256 threads, 2 blocks/SM.
// thread tile: 8 outputs (4 o-pairs) x 8 px (two quads at +0 / +64).
// =====================================================================
#define CK  16            // k-chunk
#define WTP 132           // padded row (132*4 = 528 bytes, 16B-aligned rows)

__global__ void __launch_bounds__(256, 2) conv1_kernel(
    const float* __restrict__ x, const float* __restrict__ w1,
    const float* __restrict__ b1)
{
    __shared__ float xs[CK][128];
    __shared__ float wts[CK][WTP];

    const int tid  = threadIdx.x;
    const int t    = blockIdx.x;       // px tile (128 px)
    const int half = blockIdx.y;
    const int og   = tid >> 4;         // 0..15 (8 outputs each)
    const int pg   = tid & 15;         // 0..15 (8 px each: pg*4 and 64+pg*4)
    const int obase = half * 128 + og * 8;

    const int bidx   = (t * 128) >> 12;
    const int binner = (t * 128) & 4095;
    const float* xb = x + ((size_t)bidx * CC) * 4096 + binner;

    // staging index precompute
    const int f0 = tid, f1 = tid + 256;
    const int xc0 = f0 >> 5, xp0 = f0 & 31;    // xs: 512 float4, 2/thread
    const int xc1 = f1 >> 5, xp1 = f1 & 31;
    const int wo0 = f0 >> 2, wc0 = f0 & 3;     // wts: 512 float4, 2/thread
    const int wo1 = f1 >> 2, wc1 = f1 & 3;

    // accumulators: acc[o-pair][px], init with bias
    ULL acc[4][8];
    #pragma unroll
    for (int op = 0; op < 4; op++) {
        ULL p = pack2(__ldg(&b1[obase + op * 2]), __ldg(&b1[obase + op * 2 + 1]));
        #pragma unroll
        for (int q = 0; q < 8; q++) acc[op][q] = p;
    }

    // preload chunk 0
    float4 xr0 = *reinterpret_cast<const float4*>(&xb[(size_t)xc0 * 4096 + xp0 * 4]);
    float4 xr1 = *reinterpret_cast<const float4*>(&xb[(size_t)xc1 * 4096 + xp1 * 4]);
    float4 wr0 = *reinterpret_cast<const float4*>(&w1[(half * 128 + wo0) * CC + wc0 * 4]);
    float4 wr1 = *reinterpret_cast<const float4*>(&w1[(half * 128 + wo1) * CC + wc1 * 4]);

    for (int kc = 0; kc < CC / CK; kc++) {
        __syncthreads();
        *reinterpret_cast<float4*>(&xs[xc0][xp0 * 4]) = xr0;
        *reinterpret_cast<float4*>(&xs[xc1][xp1 * 4]) = xr1;
        wts[wc0 * 4 + 0][wo0] = wr0.x; wts[wc0 * 4 + 1][wo0] = wr0.y;
        wts[wc0 * 4 + 2][wo0] = wr0.z; wts[wc0 * 4 + 3][wo0] = wr0.w;
        wts[wc1 * 4 + 0][wo1] = wr1.x; wts[wc1 * 4 + 1][wo1] = wr1.y;
        wts[wc1 * 4 + 2][wo1] = wr1.z; wts[wc1 * 4 + 3][wo1] = wr1.w;
        __syncthreads();

        if (kc + 1 < CC / CK) {
            int k = (kc + 1) * CK;
            xr0 = *reinterpret_cast<const float4*>(&xb[(size_t)(k + xc0) * 4096 + xp0 * 4]);
            xr1 = *reinterpret_cast<const float4*>(&xb[(size_t)(k + xc1) * 4096 + xp1 * 4]);
            wr0 = *reinterpret_cast<const float4*>(&w1[(half * 128 + wo0) * CC + k + wc0 * 4]);
            wr1 = *reinterpret_cast<const float4*>(&w1[(half * 128 + wo1) * CC + k + wc1 * 4]);
        }

        #pragma unroll
        for (int c = 0; c < CK; c++) {
            ulonglong2 wa = *reinterpret_cast<const ulonglong2*>(&wts[c][og * 8]);
            ulonglong2 wb = *reinterpret_cast<const ulonglong2*>(&wts[c][og * 8 + 4]);
            float4 xa = *reinterpret_cast<const float4*>(&xs[c][pg * 4]);
            float4 xc = *reinterpret_cast<const float4*>(&xs[c][64 + pg * 4]);
            ULL xp[8];
            xp[0] = pack2(xa.x, xa.x); xp[1] = pack2(xa.y, xa.y);
            xp[2] = pack2(xa.z, xa.z); xp[3] = pack2(xa.w, xa.w);
            xp[4] = pack2(xc.x, xc.x); xp[5] = pack2(xc.y, xc.y);
            xp[6] = pack2(xc.z, xc.z); xp[7] = pack2(xc.w, xc.w);
            #pragma unroll
            for (int q = 0; q < 8; q++) {
                acc[0][q] = fma2(wa.x, xp[q], acc[0][q]);
                acc[1][q] = fma2(wa.y, xp[q], acc[1][q]);
                acc[2][q] = fma2(wb.x, xp[q], acc[2][q]);
                acc[3][q] = fma2(wb.y, xp[q], acc[3][q]);
            }
        }
    }

    // relu + store h1
    const size_t pxb = (size_t)t * 128 + pg * 4;
    #pragma unroll
    for (int op = 0; op < 4; op++) {
        int o = obase + op * 2;
        float a0, b0, a1, b1v, a2, b2v, a3, b3;
        unpack2(acc[op][0], a0, b0); unpack2(acc[op][1], a1, b1v);
        unpack2(acc[op][2], a2, b2v); unpack2(acc[op][3], a3, b3);
        float4 lo = make_float4(fmaxf(a0,0.f), fmaxf(a1,0.f), fmaxf(a2,0.f), fmaxf(a3,0.f));
        float4 hi = make_float4(fmaxf(b0,0.f), fmaxf(b1v,0.f), fmaxf(b2v,0.f), fmaxf(b3,0.f));
        *reinterpret_cast<float4*>(&g_h1[(size_t)o * NPX + pxb])       = lo;
        *reinterpret_cast<float4*>(&g_h1[(size_t)(o + 1) * NPX + pxb]) = hi;
        unpack2(acc[op][4], a0, b0); unpack2(acc[op][5], a1, b1v);
        unpack2(acc[op][6], a2, b2v); unpack2(acc[op][7], a3, b3);
        float4 lo2 = make_float4(fmaxf(a0,0.f), fmaxf(a1,0.f), fmaxf(a2,0.f), fmaxf(a3,0.f));
        float4 hi2 = make_float4(fmaxf(b0,0.f), fmaxf(b1v,0.f), fmaxf(b2v,0.f), fmaxf(b3,0.f));
        *reinterpret_cast<float4*>(&g_h1[(size_t)o * NPX + pxb + 64])       = lo2;
        *reinterpret_cast<float4*>(&g_h1[(size_t)(o + 1) * NPX + pxb + 64]) = hi2;
    }
}

// =====================================================================
// Kernel 2: conv2 + relu + score partials (h2 never hits memory).
// Same tiling; k = 256 (16 chunks). Epilogue computes row/col partials.
// =====================================================================
__global__ void __launch_bounds__(256, 2) conv2_kernel(
    const float* __restrict__ w2, const float* __restrict__ b2,
    const float* __restrict__ w_row, const float* __restrict__ w_col)
{
    __shared__ float xs[CK][128];
    __shared__ float wts[CK][WTP];
    __shared__ float redr[2][8];
    __shared__ float colred[64];

    const int tid  = threadIdx.x;
    const int t    = blockIdx.x;
    const int half = blockIdx.y;
    const int og   = tid >> 4;
    const int pg   = tid & 15;
    const int obase = half * 128 + og * 8;

    if (tid < 64) colred[tid] = 0.f;

    const float* xb = g_h1 + (size_t)t * 128;   // + c*NPX + lp

    const int f0 = tid, f1 = tid + 256;
    const int xc0 = f0 >> 5, xp0 = f0 & 31;
    const int xc1 = f1 >> 5, xp1 = f1 & 31;
    const int wo0 = f0 >> 2, wc0 = f0 & 3;
    const int wo1 = f1 >> 2, wc1 = f1 & 3;

    ULL acc[4][8];
    #pragma unroll
    for (int op = 0; op < 4; op++) {
        ULL p = pack2(__ldg(&b2[obase + op * 2]), __ldg(&b2[obase + op * 2 + 1]));
        #pragma unroll
        for (int q = 0; q < 8; q++) acc[op][q] = p;
    }

    float4 xr0 = *reinterpret_cast<const float4*>(&xb[(size_t)xc0 * NPX + xp0 * 4]);
    float4 xr1 = *reinterpret_cast<const float4*>(&xb[(size_t)xc1 * NPX + xp1 * 4]);
    float4 wr0 = *reinterpret_cast<const float4*>(&w2[(half * 128 + wo0) * HID + wc0 * 4]);
    float4 wr1 = *reinterpret_cast<const float4*>(&w2[(half * 128 + wo1) * HID + wc1 * 4]);

    for (int kc = 0; kc < HID / CK; kc++) {
        __syncthreads();
        *reinterpret_cast<float4*>(&xs[xc0][xp0 * 4]) = xr0;
        *reinterpret_cast<float4*>(&xs[xc1][xp1 * 4]) = xr1;
        wts[wc0 * 4 + 0][wo0] = wr0.x; wts[wc0 * 4 + 1][wo0] = wr0.y;
        wts[wc0 * 4 + 2][wo0] = wr0.z; wts[wc0 * 4 + 3][wo0] = wr0.w;
        wts[wc1 * 4 + 0][wo1] = wr1.x; wts[wc1 * 4 + 1][wo1] = wr1.y;
        wts[wc1 * 4 + 2][wo1] = wr1.z; wts[wc1 * 4 + 3][wo1] = wr1.w;
        __syncthreads();

        if (kc + 1 < HID / CK) {
            int k = (kc + 1) * CK;
            xr0 = *reinterpret_cast<const float4*>(&xb[(size_t)(k + xc0) * NPX + xp0 * 4]);
            xr1 = *reinterpret_cast<const float4*>(&xb[(size_t)(k + xc1) * NPX + xp1 * 4]);
            wr0 = *reinterpret_cast<const float4*>(&w2[(half * 128 + wo0) * HID + k + wc0 * 4]);
            wr1 = *reinterpret_cast<const float4*>(&w2[(half * 128 + wo1) * HID + k + wc1 * 4]);
        }

        #pragma unroll
        for (int c = 0; c < CK; c++) {
            ulonglong2 wa = *reinterpret_cast<const ulonglong2*>(&wts[c][og * 8]);
            ulonglong2 wb = *reinterpret_cast<const ulonglong2*>(&wts[c][og * 8 + 4]);
            float4 xa = *reinterpret_cast<const float4*>(&xs[c][pg * 4]);
            float4 xc = *reinterpret_cast<const float4*>(&xs[c][64 + pg * 4]);
            ULL xp[8];
            xp[0] = pack2(xa.x, xa.x); xp[1] = pack2(xa.y, xa.y);
            xp[2] = pack2(xa.z, xa.z); xp[3] = pack2(xa.w, xa.w);
            xp[4] = pack2(xc.x, xc.x); xp[5] = pack2(xc.y, xc.y);
            xp[6] = pack2(xc.z, xc.z); xp[7] = pack2(xc.w, xc.w);
            #pragma unroll
            for (int q = 0; q < 8; q++) {
                acc[0][q] = fma2(wa.x, xp[q], acc[0][q]);
                acc[1][q] = fma2(wa.y, xp[q], acc[1][q]);
                acc[2][q] = fma2(wb.x, xp[q], acc[2][q]);
                acc[3][q] = fma2(wb.y, xp[q], acc[3][q]);
            }
        }
    }

    // ---- epilogue: relu + score partials (h2 stays in registers) ----
    const int bh0 = t * 2;               // quad0 row; quad1 is bh0+1 (same b)
    const int h0 = bh0 & 63;
    float rp0 = 0.f, rp1 = 0.f;
    float cp[4] = {0.f, 0.f, 0.f, 0.f};

    #pragma unroll
    for (int op = 0; op < 4; op++) {
        int o = obase + op * 2;
        float a[8][2];
        #pragma unroll
        for (int q = 0; q < 8; q++) {
            unpack2(acc[op][q], a[q][0], a[q][1]);
            a[q][0] = fmaxf(a[q][0], 0.f);
            a[q][1] = fmaxf(a[q][1], 0.f);
        }
        float4 wrA = __ldg(reinterpret_cast<const float4*>(&w_row[o * NN + pg * 4]));
        float4 wrB = __ldg(reinterpret_cast<const float4*>(&w_row[(o + 1) * NN + pg * 4]));
        rp0 += a[0][0]*wrA.x + a[1][0]*wrA.y + a[2][0]*wrA.z + a[3][0]*wrA.w
             + a[0][1]*wrB.x + a[1][1]*wrB.y + a[2][1]*wrB.z + a[3][1]*wrB.w;
        rp1 += a[4][0]*wrA.x + a[5][0]*wrA.y + a[6][0]*wrA.z + a[7][0]*wrA.w
             + a[4][1]*wrB.x + a[5][1]*wrB.y + a[6][1]*wrB.z + a[7][1]*wrB.w;
        float wc00 = __ldg(&w_col[o * NN + h0]);
        float wc01 = __ldg(&w_col[(o + 1) * NN + h0]);
        float wc10 = __ldg(&w_col[o * NN + h0 + 1]);
        float wc11 = __ldg(&w_col[(o + 1) * NN + h0 + 1]);
        #pragma unroll
        for (int q = 0; q < 4; q++) {
            cp[q] += a[q][0] * wc00 + a[q][1] * wc01
                   + a[4+q][0] * wc10 + a[4+q][1] * wc11;
        }
    }

    // row partials: full warp reduce, then per-warp slots
    #pragma unroll
    for (int m = 16; m >= 1; m >>= 1) {
        rp0 += __shfl_xor_sync(0xffffffffu, rp0, m);
        rp1 += __shfl_xor_sync(0xffffffffu, rp1, m);
    }
    if ((tid & 31) == 0) { redr[0][tid >> 5] = rp0; redr[1][tid >> 5] = rp1; }

    // col partials: fold og pairs, then smem atomic across warps
    #pragma unroll
    for (int q = 0; q < 4; q++)
        cp[q] += __shfl_xor_sync(0xffffffffu, cp[q], 16);
    if ((tid & 31) < 16) {
        #pragma unroll
        for (int q = 0; q < 4; q++) atomicAdd(&colred[pg * 4 + q], cp[q]);
    }
    __syncthreads();

    if (tid < 2) {
        float s = 0.f;
        #pragma unroll
        for (int w = 0; w < 8; w++) s += redr[tid][w];
        g_rowpart[half * (BB * NN) + bh0 + tid] = s;
    }
    if (tid < 64)
        g_cp[((size_t)half * 1024 + t) * NN + tid] = colred[tid];
}

// =====================================================================
// Kernel 3: combine partials into final scores
// =====================================================================
__global__ void combine_kernel(const float* __restrict__ b_row,
                               const float* __restrict__ b_col)
{
    int b = blockIdx.x;       // 0..31
    int w = threadIdx.x;      // 0..63
    float s = __ldg(&b_col[0]);
    #pragma unroll 4
    for (int tt = 0; tt < 32; tt++) {
        s += g_cp[(size_t)(b * 32 + tt) * NN + w];
        s += g_cp[(size_t)(1024 + b * 32 + tt) * NN + w];
    }
    g_colscore[b * NN + w] = s;
    int bh = b * NN + w;
    g_rowscore[bh] = g_rowpart[bh] + g_rowpart[BB * NN + bh] + __ldg(&b_row[0]);
}

// =====================================================================
// Kernel 4: differentiable bitonic sort -> permutation matrix P
// =====================================================================
#define PPAD 65
__global__ void __launch_bounds__(256) sort_kernel()
{
    __shared__ float P[NN * PPAD];
    __shared__ float xsh[NN];
    __shared__ float alph[32];
    __shared__ int   pa[32], pb[32];

    const int tid  = threadIdx.x;
    const int s    = blockIdx.x;
    const int kind = s >> 5;
    const int b    = s & 31;
    const float* sc = kind ? g_colscore : g_rowscore;

    if (tid < NN) xsh[tid] = sc[b * NN + tid];
    for (int idx = tid; idx < NN * NN; idx += 256) {
        int r = idx >> 6, c = idx & 63;
        P[r * PPAD + c] = (r == c) ? 1.f : 0.f;
    }
    __syncthreads();

    for (int blk = 0; blk < 6; blk++) {
        for (int lay = 0; lay <= blk; lay++) {
            int m = 1 << (blk - lay);
            if (tid < 32) {
                int q  = tid;
                int ix = ((q & ~(m - 1)) << 1) | (q & (m - 1));
                int a = ix, bidx = ix + m;
                if ((ix >> (blk + 1)) & 1) { int tswap = a; a = bidx; bidx = tswap; }
                pa[q] = a; pb[q] = bidx;
                float xa = xsh[a], xb = xsh[bidx];
                float al = atanf((xb - xa) * 50.f) * 0.31830988618379067f + 0.5f;
                alph[q] = al;
                xsh[a]    = al * xa + (1.f - al) * xb;
                xsh[bidx] = (1.f - al) * xa + al * xb;
            }
            __syncthreads();
            #pragma unroll
            for (int it = 0; it < 8; it++) {
                int idx = tid + it * 256;
                int r = idx >> 5, q = idx & 31;
                int a = pa[q], bidx = pb[q];
                float al = alph[q];
                float Pa = P[r * PPAD + a], Pb = P[r * PPAD + bidx];
                P[r * PPAD + a]    = al * Pa + (1.f - al) * Pb;
                P[r * PPAD + bidx] = (1.f - al) * Pa + al * Pb;
            }
            __syncthreads();
        }
    }

    for (int idx = tid; idx < NN * NN; idx += 256)
        g_P[(size_t)(kind * BB + b) * NN * NN + idx] = P[(idx >> 6) * PPAD + (idx & 63)];
}

// =====================================================================
// Kernel 5: out[b,c] = P_col * (P_row * X)^T     (one block per (b,c))
// =====================================================================
#define YPAD 68
struct ApplySmem {
    float Xs[NN * NN];
    float Prs[NN * PPAD];
    float Pcs[NN * PPAD];
    float Yt[NN * YPAD];
};

__global__ void __launch_bounds__(128) apply_kernel(
    const float* __restrict__ x, float* __restrict__ out)
{
    extern __shared__ unsigned char dyn_smem[];
    ApplySmem* sm = reinterpret_cast<ApplySmem*>(dyn_smem);

    const int tid = threadIdx.x;
    const int bc  = blockIdx.x;
    const int b   = bc >> 7;

    {
        const float4* xg = reinterpret_cast<const float4*>(x) + (size_t)bc * (NN * NN / 4);
        float4* Xs4 = reinterpret_cast<float4*>(sm->Xs);
        #pragma unroll
        for (int j = 0; j < 8; j++) Xs4[tid + j * 128] = xg[tid + j * 128];
    }
    {
        const float4* pr4 = reinterpret_cast<const float4*>(&g_P[(size_t)b * NN * NN]);
        const float4* pc4 = reinterpret_cast<const float4*>(&g_P[(size_t)(BB + b) * NN * NN]);
        #pragma unroll
        for (int j = 0; j < 8; j++) {
            int idx = tid + j * 128;
            int l = idx * 4, r = l >> 6, c = l & 63;
            float4 v = pr4[idx];
            float* d = &sm->Prs[r * PPAD + c];
            d[0] = v.x; d[1] = v.y; d[2] = v.z; d[3] = v.w;
            float4 u = pc4[idx];
            float* e = &sm->Pcs[r * PPAD + c];
            e[0] = u.x; e[1] = u.y; e[2] = u.z; e[3] = u.w;
        }
    }
    __syncthreads();

    const int ig = tid >> 4, kg = tid & 15;
    const int i0 = ig * 8,   k0 = kg * 4;

    ULL acc[8][2];
    #pragma unroll
    for (int ii = 0; ii < 8; ii++) { acc[ii][0] = 0ull; acc[ii][1] = 0ull; }

    #pragma unroll 4
    for (int j = 0; j < NN; j++) {
        const ULL* xp = reinterpret_cast<const ULL*>(&sm->Xs[j * NN + k0]);
        ULL xv0 = xp[0], xv1 = xp[1];
        #pragma unroll
        for (int ii = 0; ii < 8; ii++) {
            float p = sm->Prs[(i0 + ii) * PPAD + j];
            ULL pp = pack2(p, p);
            acc[ii][0] = fma2(xv0, pp, acc[ii][0]);
            acc[ii][1] = fma2(xv1, pp, acc[ii][1]);
        }
    }
    {
        float yv[8][4];
        #pragma unroll
        for (int ii = 0; ii < 8; ii++) {
            unpack2(acc[ii][0], yv[ii][0], yv[ii][1]);
            unpack2(acc[ii][1], yv[ii][2], yv[ii][3]);
        }
        #pragma unroll
        for (int kk = 0; kk < 4; kk++) {
            float4 v0 = make_float4(yv[0][kk], yv[1][kk], yv[2][kk], yv[3][kk]);
            float4 v1 = make_float4(yv[4][kk], yv[5][kk], yv[6][kk], yv[7][kk]);
            *reinterpret_cast<float4*>(&sm->Yt[(k0 + kk) * YPAD + i0])     = v0;
            *reinterpret_cast<float4*>(&sm->Yt[(k0 + kk) * YPAD + i0 + 4]) = v1;
        }
    }
    __syncthreads();

    #pragma unroll
    for (int ii = 0; ii < 8; ii++) { acc[ii][0] = 0ull; acc[ii][1] = 0ull; }

    #pragma unroll 4
    for (int j = 0; j < NN; j++) {
        const ULL* yp = reinterpret_cast<const ULL*>(&sm->Yt[j * YPAD + k0]);
        ULL yv0 = yp[0], yv1 = yp[1];
        #pragma unroll
        for (int ii = 0; ii < 8; ii++) {
            float p = sm->Pcs[(i0 + ii) * PPAD + j];
            ULL pp = pack2(p, p);
            acc[ii][0] = fma2(yv0, pp, acc[ii][0]);
            acc[ii][1] = fma2(yv1, pp, acc[ii][1]);
        }
    }

    float* og = out + (size_t)bc * NN * NN;
    #pragma unroll
    for (int ii = 0; ii < 8; ii++) {
        float o0, o1, o2, o3;
        unpack2(acc[ii][0], o0, o1);
        unpack2(acc[ii][1], o2, o3);
        *reinterpret_cast<float4*>(&og[(ii + i0) * NN + k0]) = make_float4(o0, o1, o2, o3);
    }
}

// =====================================================================
// launcher
// =====================================================================
extern "C" void kernel_launch(void* const* d_in, const int* in_sizes, int n_in,
                              void* d_out, int out_size)
{
    const float* x     = (const float*)d_in[0];
    const float* w1    = (const float*)d_in[1];
    const float* b1    = (const float*)d_in[2];
    const float* w2    = (const float*)d_in[3];
    const float* b2    = (const float*)d_in[4];
    const float* w_row = (const float*)d_in[5];
    const float* b_row = (const float*)d_in[6];
    const float* w_col = (const float*)d_in[7];
    const float* b_col = (const float*)d_in[8];
    float* out = (float*)d_out;

    const int apply_smem = (int)sizeof(ApplySmem);
    cudaFuncSetAttribute(apply_kernel, cudaFuncAttributeMaxDynamicSharedMemorySize, apply_smem);

    conv1_kernel<<<dim3(1024, 2), 256>>>(x, w1, b1);
    conv2_kernel<<<dim3(1024, 2), 256>>>(w2, b2, w_row, w_col);
    combine_kernel<<<BB, NN>>>(b_row, b_col);
    sort_kernel<<<2 * BB, 256>>>();
    apply_kernel<<<BB * CC, 128, apply_smem>>>(x, out);
}